// round 1
// baseline (speedup 1.0000x reference)
#include <cuda_runtime.h>
#include <math.h>

#define T 8
#define NN 100000
#define H 128
#define NIN 64
#define NPB 8
#define MROWS 64
#define AS_LD 132
#define XS_LD 68
#define LN_EPS 1e-5f
#define SMEM_FLOATS (3*MROWS*AS_LD + 16*H + 512)
#define SMEM_BYTES (SMEM_FLOATS*4)

// ---------------- folded-weight scratch (device globals; no allocs) ----------
__device__ float g_hb[T*H];       // proj_b + pe[t]
__device__ float g_wqT[H*H];      // (q_w @ proj_w)^T  -> [j][c]
__device__ float g_wkT[H*H];
__device__ float g_wvT[H*H];      // (fc_w @ v_w @ proj_w)^T
__device__ float g_tmpVP[H*H];    // v_w @ proj_w, row-major [c][j]
__device__ float g_cvt[T*H];
__device__ float g_resT[NIN*H];   // res_w^T -> [j][c]
__device__ float g_cq[T*H];
__device__ float g_ck[T*H];
__device__ float g_cv[T*H];

// pe computed in double to match numpy float64 -> float32 cast
__global__ void prep0_kernel(const float* __restrict__ proj_b) {
    int t = blockIdx.x, m = threadIdx.x;
    int i2 = m & ~1;
    double div = exp((double)i2 * (-log(100000.0)) / (double)H);
    double arg = (double)(t + 1) * div;
    double pe = (m & 1) ? cos(arg) : sin(arg);
    g_hb[t*H + m] = proj_b[m] + (float)pe;
}

__global__ void prep1_kernel(const float* __restrict__ proj_w,
                             const float* __restrict__ q_w,
                             const float* __restrict__ k_w,
                             const float* __restrict__ v_w,
                             const float* __restrict__ res_w) {
    int c = blockIdx.x, j = threadIdx.x;
    float sq = 0.f, sk = 0.f, sv = 0.f;
    for (int m = 0; m < H; m++) {
        float p = proj_w[m*H + j];
        sq = fmaf(q_w[c*H + m], p, sq);
        sk = fmaf(k_w[c*H + m], p, sk);
        sv = fmaf(v_w[c*H + m], p, sv);
    }
    g_wqT[j*H + c] = sq;
    g_wkT[j*H + c] = sk;
    g_tmpVP[c*H + j] = sv;
    if (j < NIN) g_resT[j*H + c] = res_w[c*NIN + j];
    if (j < T) {
        float a = 0.f, b = 0.f, vv = 0.f;
        for (int m = 0; m < H; m++) {
            float hb = g_hb[j*H + m];
            a  = fmaf(q_w[c*H + m], hb, a);
            b  = fmaf(k_w[c*H + m], hb, b);
            vv = fmaf(v_w[c*H + m], hb, vv);
        }
        g_cq[j*H + c] = a;
        g_ck[j*H + c] = b;
        g_cvt[j*H + c] = vv;
    }
}

__global__ void prep2_kernel(const float* __restrict__ fc_w) {
    int c = blockIdx.x, j = threadIdx.x;
    float s = 0.f;
    for (int m = 0; m < H; m++) s = fmaf(fc_w[c*H + m], g_tmpVP[m*H + j], s);
    g_wvT[j*H + c] = s;
    if (j < T) {
        float s2 = 0.f;
        for (int m = 0; m < H; m++) s2 = fmaf(fc_w[c*H + m], g_cvt[j*H + m], s2);
        g_cv[j*H + c] = s2;
    }
}

// ---------------- main fused kernel ----------------
template<int K, int LDA>
__device__ __forceinline__ void gemm_tile(const float* __restrict__ A,
        const float* __restrict__ wT, float* Ws, float (&acc)[4][8],
        int tid, int r0, int c0)
{
#pragma unroll
    for (int i = 0; i < 4; i++)
#pragma unroll
        for (int q = 0; q < 8; q++) acc[i][q] = 0.f;
    for (int j0 = 0; j0 < K; j0 += 16) {
        // stage 16 x 128 weight chunk into SMEM (coalesced float4)
        const float4* src = (const float4*)(wT + j0*H);
        float4* dst = (float4*)Ws;
        dst[tid]       = src[tid];
        dst[tid + 256] = src[tid + 256];
        __syncthreads();
#pragma unroll
        for (int jj = 0; jj < 16; jj++) {
            float a0 = A[(r0+0)*LDA + j0 + jj];
            float a1 = A[(r0+1)*LDA + j0 + jj];
            float a2 = A[(r0+2)*LDA + j0 + jj];
            float a3 = A[(r0+3)*LDA + j0 + jj];
            float4 w0 = *(const float4*)(Ws + jj*H + c0);
            float4 w1 = *(const float4*)(Ws + jj*H + c0 + 4);
            float wv[8] = {w0.x,w0.y,w0.z,w0.w,w1.x,w1.y,w1.z,w1.w};
#pragma unroll
            for (int q = 0; q < 8; q++) {
                acc[0][q] = fmaf(a0, wv[q], acc[0][q]);
                acc[1][q] = fmaf(a1, wv[q], acc[1][q]);
                acc[2][q] = fmaf(a2, wv[q], acc[2][q]);
                acc[3][q] = fmaf(a3, wv[q], acc[3][q]);
            }
        }
        __syncthreads();
    }
}

__device__ __forceinline__ void store_bias(float* Os, const float* __restrict__ cb,
        float (&acc)[4][8], int r0, int c0)
{
#pragma unroll
    for (int i = 0; i < 4; i++) {
        int r = r0 + i, t = r & 7;
        float4 b0 = *(const float4*)(cb + t*H + c0);
        float4 b1 = *(const float4*)(cb + t*H + c0 + 4);
        float bb[8] = {b0.x,b0.y,b0.z,b0.w,b1.x,b1.y,b1.z,b1.w};
#pragma unroll
        for (int q = 0; q < 8; q++)
            Os[r*AS_LD + c0 + q] = acc[i][q] + bb[q];
    }
}

__global__ void __launch_bounds__(256, 2) htgnn_main(
    const float* __restrict__ inter, const float* __restrict__ x,
    const float* __restrict__ fc_b, const float* __restrict__ res_b,
    const float* __restrict__ res_alpha, const float* __restrict__ ln_g,
    const float* __restrict__ ln_b, float* __restrict__ out)
{
    extern __shared__ __align__(16) float smem[];
    float* As = smem;                      // [64][132] inter rows (node-local*8 + t)
    float* Qs = As + MROWS*AS_LD;          // [64][132] Q, later V
    float* Ks = Qs + MROWS*AS_LD;          // [64][132] K, later Xs
    float* Ws = Ks + MROWS*AS_LD;          // [16][128] weight chunk
    float* Ss = Ws + 16*H;                 // [8][8][8] softmax probs
    float* Xs = Ks;                        // [64][68]

    const int tid = threadIdx.x;
    const int node0 = blockIdx.x * NPB;
    const int ty = tid >> 4;
    const int tx = tid & 15;
    const int r0 = ty * 4;
    const int c0 = tx * 8;

    // ---- load inter -> As (coalesced float4) ----
    {
        int nl = tid >> 5;      // 0..7 node-local
        int c4 = tid & 31;      // 0..31 float4 column
#pragma unroll
        for (int t = 0; t < T; t++) {
            float4 v = *(const float4*)(inter + ((size_t)t*NN + node0 + nl)*H + c4*4);
            *(float4*)(As + (nl*T + t)*AS_LD + c4*4) = v;
        }
    }
    __syncthreads();

    float acc[4][8];

    // ---- Q = A @ WqT + cq ; K = A @ WkT + ck ----
    gemm_tile<H, AS_LD>(As, g_wqT, Ws, acc, tid, r0, c0);
    store_bias(Qs, g_cq, acc, r0, c0);
    gemm_tile<H, AS_LD>(As, g_wkT, Ws, acc, tid, r0, c0);
    store_bias(Ks, g_ck, acc, r0, c0);
    __syncthreads();

    // ---- scores = softmax(Q K^T) per node (warp w -> node w) ----
    {
        int w = tid >> 5, lane = tid & 31;
        int s = lane & 7, t0v = lane >> 3;          // t0v 0..3, second pair t0v+4
        const float* Qr0 = Qs + (w*8 + t0v)*AS_LD;
        const float* Qr1 = Qs + (w*8 + t0v + 4)*AS_LD;
        const float* Kr  = Ks + (w*8 + s)*AS_LD;
        float d0 = 0.f, d1 = 0.f;
#pragma unroll
        for (int j4 = 0; j4 < H/4; j4++) {
            float4 kv = *(const float4*)(Kr  + j4*4);
            float4 q0 = *(const float4*)(Qr0 + j4*4);
            float4 q1 = *(const float4*)(Qr1 + j4*4);
            d0 += q0.x*kv.x + q0.y*kv.y + q0.z*kv.z + q0.w*kv.w;
            d1 += q1.x*kv.x + q1.y*kv.y + q1.z*kv.z + q1.w*kv.w;
        }
        float m0 = d0, m1 = d1;
#pragma unroll
        for (int off = 1; off < 8; off <<= 1) {
            m0 = fmaxf(m0, __shfl_xor_sync(0xffffffffu, m0, off));
            m1 = fmaxf(m1, __shfl_xor_sync(0xffffffffu, m1, off));
        }
        float e0 = expf(d0 - m0), e1 = expf(d1 - m1);
        float s0 = e0, s1 = e1;
#pragma unroll
        for (int off = 1; off < 8; off <<= 1) {
            s0 += __shfl_xor_sync(0xffffffffu, s0, off);
            s1 += __shfl_xor_sync(0xffffffffu, s1, off);
        }
        Ss[w*64 + t0v*8 + s]     = e0 / s0;
        Ss[w*64 + (t0v+4)*8 + s] = e1 / s1;
    }
    __syncthreads();   // K reads done -> safe to overwrite Ks with Xs

    // ---- load x -> Xs (reuses Ks buffer) ----
#pragma unroll
    for (int ii = 0; ii < 4; ii++) {
        int g = ii*256 + tid;             // 0..1023
        int t = g >> 7, rem = g & 127, nl = rem >> 4, c4 = rem & 15;
        float4 v = *(const float4*)(x + ((size_t)t*NN + node0 + nl)*NIN + c4*4);
        *(float4*)(Xs + (nl*T + t)*XS_LD + c4*4) = v;
    }

    // ---- V2 = A @ WvT + cv (fc folded in); overwrites Qs ----
    gemm_tile<H, AS_LD>(As, g_wvT, Ws, acc, tid, r0, c0);
    store_bias(Qs, g_cv, acc, r0, c0);

    // ---- res = x @ res_w^T (K=64), into registers ----
    float rc[4][8];
    gemm_tile<NIN, XS_LD>(Xs, g_resT, Ws, rc, tid, r0, c0);

    // ---- attention output: o = S @ V2 ----
    float o[4][8];
#pragma unroll
    for (int i = 0; i < 4; i++) {
        int r = r0 + i, node = r >> 3, t = r & 7;
        const float* Sp = Ss + node*64 + t*8;
        const float* Vb = Qs + (node*8)*AS_LD + c0;
#pragma unroll
        for (int q = 0; q < 8; q++) o[i][q] = 0.f;
#pragma unroll
        for (int s = 0; s < T; s++) {
            float p = Sp[s];
            const float* Vr = Vb + s*AS_LD;
#pragma unroll
            for (int q = 0; q < 8; q++) o[i][q] = fmaf(p, Vr[q], o[i][q]);
        }
    }

    // ---- epilogue: relu(o+fc_b), gated residual, LayerNorm, store ----
    float alpha = 1.f / (1.f + expf(-res_alpha[0]));
    float beta  = 1.f - alpha;
    float4 fb0 = *(const float4*)(fc_b + c0);
    float4 fb1 = *(const float4*)(fc_b + c0 + 4);
    float4 rb0 = *(const float4*)(res_b + c0);
    float4 rb1 = *(const float4*)(res_b + c0 + 4);
    float4 lg0 = *(const float4*)(ln_g + c0);
    float4 lg1 = *(const float4*)(ln_g + c0 + 4);
    float4 lb0 = *(const float4*)(ln_b + c0);
    float4 lb1 = *(const float4*)(ln_b + c0 + 4);
    float fb[8] = {fb0.x,fb0.y,fb0.z,fb0.w,fb1.x,fb1.y,fb1.z,fb1.w};
    float rb[8] = {rb0.x,rb0.y,rb0.z,rb0.w,rb1.x,rb1.y,rb1.z,rb1.w};
    float lg[8] = {lg0.x,lg0.y,lg0.z,lg0.w,lg1.x,lg1.y,lg1.z,lg1.w};
    float lb[8] = {lb0.x,lb0.y,lb0.z,lb0.w,lb1.x,lb1.y,lb1.z,lb1.w};

#pragma unroll
    for (int i = 0; i < 4; i++) {
        int r = r0 + i, t = r & 7;
        size_t n = (size_t)node0 + (r >> 3);
        float vbuf[8];
        float sum = 0.f, sq = 0.f;
#pragma unroll
        for (int q = 0; q < 8; q++) {
            float hv  = fmaxf(o[i][q] + fb[q], 0.f);
            float rv  = rc[i][q] + rb[q];
            float val = hv*alpha + rv*beta;
            vbuf[q] = val;
            sum += val;
            sq = fmaf(val, val, sq);
        }
        // row reduction over the 16 lanes sharing this row (xor <= 8 stays in half-warp)
#pragma unroll
        for (int off = 1; off < 16; off <<= 1) {
            sum += __shfl_xor_sync(0xffffffffu, sum, off);
            sq  += __shfl_xor_sync(0xffffffffu, sq,  off);
        }
        float mu  = sum * (1.f/(float)H);
        float var = sq * (1.f/(float)H) - mu*mu;
        float inv = rsqrtf(var + LN_EPS);
#pragma unroll
        for (int q = 0; q < 8; q++)
            vbuf[q] = (vbuf[q] - mu) * inv * lg[q] + lb[q];
        float4 o0 = make_float4(vbuf[0], vbuf[1], vbuf[2], vbuf[3]);
        float4 o1 = make_float4(vbuf[4], vbuf[5], vbuf[6], vbuf[7]);
        float* op = out + ((size_t)t*NN + n)*H + c0;
        *(float4*)op       = o0;
        *(float4*)(op + 4) = o1;
    }
}

extern "C" void kernel_launch(void* const* d_in, const int* in_sizes, int n_in,
                              void* d_out, int out_size) {
    (void)in_sizes; (void)n_in; (void)out_size;
    const float* inter     = (const float*)d_in[0];
    const float* x         = (const float*)d_in[1];
    const float* proj_w    = (const float*)d_in[2];
    const float* proj_b    = (const float*)d_in[3];
    const float* q_w       = (const float*)d_in[4];
    const float* k_w       = (const float*)d_in[5];
    const float* v_w       = (const float*)d_in[6];
    const float* fc_w      = (const float*)d_in[7];
    const float* fc_b      = (const float*)d_in[8];
    const float* res_w     = (const float*)d_in[9];
    const float* res_b     = (const float*)d_in[10];
    const float* res_alpha = (const float*)d_in[11];
    const float* ln_g      = (const float*)d_in[12];
    const float* ln_b      = (const float*)d_in[13];
    float* out = (float*)d_out;

    cudaFuncSetAttribute(htgnn_main, cudaFuncAttributeMaxDynamicSharedMemorySize,
                         SMEM_BYTES);

    prep0_kernel<<<T, H>>>(proj_b);
    prep1_kernel<<<H, H>>>(proj_w, q_w, k_w, v_w, res_w);
    prep2_kernel<<<H, H>>>(fc_w);
    htgnn_main<<<NN/NPB, 256, SMEM_BYTES>>>(inter, x, fc_b, res_b, res_alpha,
                                            ln_g, ln_b, out);
}

// round 2
// speedup vs baseline: 1.0010x; 1.0010x over previous
#include <cuda_runtime.h>
#include <math.h>

#define T 8
#define NN 100000
#define H 128
#define NIN 64
#define NPB 8
#define MROWS 64
#define AS_LD 132
#define XS_LD 68
#define LN_EPS 1e-5f
#define SMEM_FLOATS (3*MROWS*AS_LD + 16*H + 512)
#define SMEM_BYTES (SMEM_FLOATS*4)

// ---------------- folded-weight scratch (device globals; no allocs) ----------
__device__ float g_hb[T*H];       // proj_b + pe[t]
__device__ float g_wqT[H*H];      // (q_w @ proj_w)^T  -> [j][c]
__device__ float g_wkT[H*H];
__device__ float g_wvT[H*H];      // (fc_w @ v_w @ proj_w)^T
__device__ float g_tmpVP[H*H];    // v_w @ proj_w, row-major [c][j]
__device__ float g_cvt[T*H];
__device__ float g_resT[NIN*H];   // res_w^T -> [j][c]
__device__ float g_cq[T*H];
__device__ float g_ck[T*H];
__device__ float g_cv[T*H];

// pe computed in double to match numpy float64 -> float32 cast
__global__ void prep0_kernel(const float* __restrict__ proj_b) {
    int t = blockIdx.x, m = threadIdx.x;
    int i2 = m & ~1;
    double div = exp((double)i2 * (-log(100000.0)) / (double)H);
    double arg = (double)(t + 1) * div;
    double pe = (m & 1) ? cos(arg) : sin(arg);
    g_hb[t*H + m] = proj_b[m] + (float)pe;
}

__global__ void prep1_kernel(const float* __restrict__ proj_w,
                             const float* __restrict__ q_w,
                             const float* __restrict__ k_w,
                             const float* __restrict__ v_w,
                             const float* __restrict__ res_w) {
    int c = blockIdx.x, j = threadIdx.x;
    float sq = 0.f, sk = 0.f, sv = 0.f;
    for (int m = 0; m < H; m++) {
        float p = proj_w[m*H + j];
        sq = fmaf(q_w[c*H + m], p, sq);
        sk = fmaf(k_w[c*H + m], p, sk);
        sv = fmaf(v_w[c*H + m], p, sv);
    }
    g_wqT[j*H + c] = sq;
    g_wkT[j*H + c] = sk;
    g_tmpVP[c*H + j] = sv;
    if (j < NIN) g_resT[j*H + c] = res_w[c*NIN + j];
    if (j < T) {
        float a = 0.f, b = 0.f, vv = 0.f;
        for (int m = 0; m < H; m++) {
            float hb = g_hb[j*H + m];
            a  = fmaf(q_w[c*H + m], hb, a);
            b  = fmaf(k_w[c*H + m], hb, b);
            vv = fmaf(v_w[c*H + m], hb, vv);
        }
        g_cq[j*H + c] = a;
        g_ck[j*H + c] = b;
        g_cvt[j*H + c] = vv;
    }
}

__global__ void prep2_kernel(const float* __restrict__ fc_w) {
    int c = blockIdx.x, j = threadIdx.x;
    float s = 0.f;
    for (int m = 0; m < H; m++) s = fmaf(fc_w[c*H + m], g_tmpVP[m*H + j], s);
    g_wvT[j*H + c] = s;
    if (j < T) {
        float s2 = 0.f;
        for (int m = 0; m < H; m++) s2 = fmaf(fc_w[c*H + m], g_cvt[j*H + m], s2);
        g_cv[j*H + c] = s2;
    }
}

// ---------------- main fused kernel ----------------
template<int K, int LDA>
__device__ __forceinline__ void gemm_tile(const float* __restrict__ A,
        const float* __restrict__ wT, float* Ws, float (&acc)[4][8],
        int tid, int r0, int c0)
{
#pragma unroll
    for (int i = 0; i < 4; i++)
#pragma unroll
        for (int q = 0; q < 8; q++) acc[i][q] = 0.f;
    for (int j0 = 0; j0 < K; j0 += 16) {
        // stage 16 x 128 weight chunk into SMEM (coalesced float4)
        const float4* src = (const float4*)(wT + j0*H);
        float4* dst = (float4*)Ws;
        dst[tid]       = src[tid];
        dst[tid + 256] = src[tid + 256];
        __syncthreads();
#pragma unroll
        for (int jj = 0; jj < 16; jj++) {
            float a0 = A[(r0+0)*LDA + j0 + jj];
            float a1 = A[(r0+1)*LDA + j0 + jj];
            float a2 = A[(r0+2)*LDA + j0 + jj];
            float a3 = A[(r0+3)*LDA + j0 + jj];
            float4 w0 = *(const float4*)(Ws + jj*H + c0);
            float4 w1 = *(const float4*)(Ws + jj*H + c0 + 4);
            float wv[8] = {w0.x,w0.y,w0.z,w0.w,w1.x,w1.y,w1.z,w1.w};
#pragma unroll
            for (int q = 0; q < 8; q++) {
                acc[0][q] = fmaf(a0, wv[q], acc[0][q]);
                acc[1][q] = fmaf(a1, wv[q], acc[1][q]);
                acc[2][q] = fmaf(a2, wv[q], acc[2][q]);
                acc[3][q] = fmaf(a3, wv[q], acc[3][q]);
            }
        }
        __syncthreads();
    }
}

__device__ __forceinline__ void store_bias(float* Os, const float* __restrict__ cb,
        float (&acc)[4][8], int r0, int c0)
{
#pragma unroll
    for (int i = 0; i < 4; i++) {
        int r = r0 + i, t = r & 7;
        float4 b0 = *(const float4*)(cb + t*H + c0);
        float4 b1 = *(const float4*)(cb + t*H + c0 + 4);
        float bb[8] = {b0.x,b0.y,b0.z,b0.w,b1.x,b1.y,b1.z,b1.w};
#pragma unroll
        for (int q = 0; q < 8; q++)
            Os[r*AS_LD + c0 + q] = acc[i][q] + bb[q];
    }
}

__global__ void __launch_bounds__(256, 2) htgnn_main(
    const float* __restrict__ inter, const float* __restrict__ x,
    const float* __restrict__ fc_b, const float* __restrict__ res_b,
    const float* __restrict__ res_alpha, const float* __restrict__ ln_g,
    const float* __restrict__ ln_b, float* __restrict__ out)
{
    extern __shared__ __align__(16) float smem[];
    float* As = smem;                      // [64][132] inter rows (node-local*8 + t)
    float* Qs = As + MROWS*AS_LD;          // [64][132] Q, later V
    float* Ks = Qs + MROWS*AS_LD;          // [64][132] K, later Xs
    float* Ws = Ks + MROWS*AS_LD;          // [16][128] weight chunk
    float* Ss = Ws + 16*H;                 // [8][8][8] softmax probs
    float* Xs = Ks;                        // [64][68]

    const int tid = threadIdx.x;
    const int node0 = blockIdx.x * NPB;
    const int ty = tid >> 4;
    const int tx = tid & 15;
    const int r0 = ty * 4;
    const int c0 = tx * 8;

    // ---- load inter -> As (coalesced float4) ----
    {
        int nl = tid >> 5;      // 0..7 node-local
        int c4 = tid & 31;      // 0..31 float4 column
#pragma unroll
        for (int t = 0; t < T; t++) {
            float4 v = *(const float4*)(inter + ((size_t)t*NN + node0 + nl)*H + c4*4);
            *(float4*)(As + (nl*T + t)*AS_LD + c4*4) = v;
        }
    }
    __syncthreads();

    float acc[4][8];

    // ---- Q = A @ WqT + cq ; K = A @ WkT + ck ----
    gemm_tile<H, AS_LD>(As, g_wqT, Ws, acc, tid, r0, c0);
    store_bias(Qs, g_cq, acc, r0, c0);
    gemm_tile<H, AS_LD>(As, g_wkT, Ws, acc, tid, r0, c0);
    store_bias(Ks, g_ck, acc, r0, c0);
    __syncthreads();

    // ---- scores = softmax(Q K^T) per node (warp w -> node w) ----
    {
        int w = tid >> 5, lane = tid & 31;
        int s = lane & 7, t0v = lane >> 3;          // t0v 0..3, second pair t0v+4
        const float* Qr0 = Qs + (w*8 + t0v)*AS_LD;
        const float* Qr1 = Qs + (w*8 + t0v + 4)*AS_LD;
        const float* Kr  = Ks + (w*8 + s)*AS_LD;
        float d0 = 0.f, d1 = 0.f;
#pragma unroll
        for (int j4 = 0; j4 < H/4; j4++) {
            float4 kv = *(const float4*)(Kr  + j4*4);
            float4 q0 = *(const float4*)(Qr0 + j4*4);
            float4 q1 = *(const float4*)(Qr1 + j4*4);
            d0 += q0.x*kv.x + q0.y*kv.y + q0.z*kv.z + q0.w*kv.w;
            d1 += q1.x*kv.x + q1.y*kv.y + q1.z*kv.z + q1.w*kv.w;
        }
        float m0 = d0, m1 = d1;
#pragma unroll
        for (int off = 1; off < 8; off <<= 1) {
            m0 = fmaxf(m0, __shfl_xor_sync(0xffffffffu, m0, off));
            m1 = fmaxf(m1, __shfl_xor_sync(0xffffffffu, m1, off));
        }
        float e0 = expf(d0 - m0), e1 = expf(d1 - m1);
        float s0 = e0, s1 = e1;
#pragma unroll
        for (int off = 1; off < 8; off <<= 1) {
            s0 += __shfl_xor_sync(0xffffffffu, s0, off);
            s1 += __shfl_xor_sync(0xffffffffu, s1, off);
        }
        Ss[w*64 + t0v*8 + s]     = e0 / s0;
        Ss[w*64 + (t0v+4)*8 + s] = e1 / s1;
    }
    __syncthreads();   // K reads done -> safe to overwrite Ks with Xs

    // ---- load x -> Xs (reuses Ks buffer) ----
#pragma unroll
    for (int ii = 0; ii < 4; ii++) {
        int g = ii*256 + tid;             // 0..1023
        int t = g >> 7, rem = g & 127, nl = rem >> 4, c4 = rem & 15;
        float4 v = *(const float4*)(x + ((size_t)t*NN + node0 + nl)*NIN + c4*4);
        *(float4*)(Xs + (nl*T + t)*XS_LD + c4*4) = v;
    }

    // ---- V2 = A @ WvT + cv (fc folded in); overwrites Qs ----
    gemm_tile<H, AS_LD>(As, g_wvT, Ws, acc, tid, r0, c0);
    store_bias(Qs, g_cv, acc, r0, c0);

    // ---- res = x @ res_w^T (K=64), into registers ----
    float rc[4][8];
    gemm_tile<NIN, XS_LD>(Xs, g_resT, Ws, rc, tid, r0, c0);

    // ---- attention output: o = S @ V2 ----
    float o[4][8];
#pragma unroll
    for (int i = 0; i < 4; i++) {
        int r = r0 + i, node = r >> 3, t = r & 7;
        const float* Sp = Ss + node*64 + t*8;
        const float* Vb = Qs + (node*8)*AS_LD + c0;
#pragma unroll
        for (int q = 0; q < 8; q++) o[i][q] = 0.f;
#pragma unroll
        for (int s = 0; s < T; s++) {
            float p = Sp[s];
            const float* Vr = Vb + s*AS_LD;
#pragma unroll
            for (int q = 0; q < 8; q++) o[i][q] = fmaf(p, Vr[q], o[i][q]);
        }
    }

    // ---- epilogue: relu(o+fc_b), gated residual, LayerNorm, store ----
    float alpha = 1.f / (1.f + expf(-res_alpha[0]));
    float beta  = 1.f - alpha;
    float4 fb0 = *(const float4*)(fc_b + c0);
    float4 fb1 = *(const float4*)(fc_b + c0 + 4);
    float4 rb0 = *(const float4*)(res_b + c0);
    float4 rb1 = *(const float4*)(res_b + c0 + 4);
    float4 lg0 = *(const float4*)(ln_g + c0);
    float4 lg1 = *(const float4*)(ln_g + c0 + 4);
    float4 lb0 = *(const float4*)(ln_b + c0);
    float4 lb1 = *(const float4*)(ln_b + c0 + 4);
    float fb[8] = {fb0.x,fb0.y,fb0.z,fb0.w,fb1.x,fb1.y,fb1.z,fb1.w};
    float rb[8] = {rb0.x,rb0.y,rb0.z,rb0.w,rb1.x,rb1.y,rb1.z,rb1.w};
    float lg[8] = {lg0.x,lg0.y,lg0.z,lg0.w,lg1.x,lg1.y,lg1.z,lg1.w};
    float lb[8] = {lb0.x,lb0.y,lb0.z,lb0.w,lb1.x,lb1.y,lb1.z,lb1.w};

#pragma unroll
    for (int i = 0; i < 4; i++) {
        int r = r0 + i, t = r & 7;
        size_t n = (size_t)node0 + (r >> 3);
        float vbuf[8];
        float sum = 0.f, sq = 0.f;
#pragma unroll
        for (int q = 0; q < 8; q++) {
            float hv  = fmaxf(o[i][q] + fb[q], 0.f);
            float rv  = rc[i][q] + rb[q];
            float val = hv*alpha + rv*beta;
            vbuf[q] = val;
            sum += val;
            sq = fmaf(val, val, sq);
        }
        // row reduction over the 16 lanes sharing this row (xor <= 8 stays in half-warp)
#pragma unroll
        for (int off = 1; off < 16; off <<= 1) {
            sum += __shfl_xor_sync(0xffffffffu, sum, off);
            sq  += __shfl_xor_sync(0xffffffffu, sq,  off);
        }
        float mu  = sum * (1.f/(float)H);
        float var = sq * (1.f/(float)H) - mu*mu;
        float inv = rsqrtf(var + LN_EPS);
#pragma unroll
        for (int q = 0; q < 8; q++)
            vbuf[q] = (vbuf[q] - mu) * inv * lg[q] + lb[q];
        float4 o0 = make_float4(vbuf[0], vbuf[1], vbuf[2], vbuf[3]);
        float4 o1 = make_float4(vbuf[4], vbuf[5], vbuf[6], vbuf[7]);
        float* op = out + ((size_t)t*NN + n)*H + c0;
        *(float4*)op       = o0;
        *(float4*)(op + 4) = o1;
    }
}

extern "C" void kernel_launch(void* const* d_in, const int* in_sizes, int n_in,
                              void* d_out, int out_size) {
    (void)in_sizes; (void)n_in; (void)out_size;
    const float* inter     = (const float*)d_in[0];
    const float* x         = (const float*)d_in[1];
    const float* proj_w    = (const float*)d_in[2];
    const float* proj_b    = (const float*)d_in[3];
    const float* q_w       = (const float*)d_in[4];
    const float* k_w       = (const float*)d_in[5];
    const float* v_w       = (const float*)d_in[6];
    const float* fc_w      = (const float*)d_in[7];
    const float* fc_b      = (const float*)d_in[8];
    const float* res_w     = (const float*)d_in[9];
    const float* res_b     = (const float*)d_in[10];
    const float* res_alpha = (const float*)d_in[11];
    const float* ln_g      = (const float*)d_in[12];
    const float* ln_b      = (const float*)d_in[13];
    float* out = (float*)d_out;

    cudaFuncSetAttribute(htgnn_main, cudaFuncAttributeMaxDynamicSharedMemorySize,
                         SMEM_BYTES);

    prep0_kernel<<<T, H>>>(proj_b);
    prep1_kernel<<<H, H>>>(proj_w, q_w, k_w, v_w, res_w);
    prep2_kernel<<<H, H>>>(fc_w);
    htgnn_main<<<NN/NPB, 256, SMEM_BYTES>>>(inter, x, fc_b, res_b, res_alpha,
                                            ln_g, ln_b, out);
}

// round 4
// speedup vs baseline: 3.1311x; 3.1281x over previous
#include <cuda_runtime.h>
#include <cuda_fp16.h>
#include <math.h>
#include <stdint.h>

#define T 8
#define NN 100000
#define H 128
#define NIN 64
#define LN_EPS 1e-5f
#define WSCALE 64.f
#define WSCALE_INV 0.015625f

// ---------------- folded weights in mma-B-fragment layout ----------------
// For (n,k): nt=n/8, kt=k/16, lane=((n&7)<<2)|((k>>1)&3), grp=(k>>3)&1, p=k&1
// uint4 slot idx = (nt*KT+kt)*32+lane ; halves: [hi_k0pair, hi_k8pair, lo_k0, lo_k8]
__device__ __align__(16) __half g_wqF[16*8*32*8];
__device__ __align__(16) __half g_wkF[16*8*32*8];
__device__ __align__(16) __half g_wvF[16*8*32*8];
__device__ __align__(16) __half g_wrF[16*4*32*8];
__device__ float g_cq[T*H], g_ck[T*H], g_cv[T*H];   // [t][c]
__device__ float g_hb[T*H];
__device__ float g_tmpVP[H*H];
__device__ float g_cvt[T*H];

template<int KT>
__device__ __forceinline__ void writeFrag(__half* wf, int n, int k, float w) {
    int nt = n >> 3, kt = k >> 4;
    int lane = ((n & 7) << 2) | ((k >> 1) & 3);
    int grp = (k >> 3) & 1, p = k & 1;
    int base = ((nt*KT + kt)*32 + lane)*8;
    __half h = __float2half_rn(w);
    float r = w - __half2float(h);
    wf[base + grp*2 + p]     = __float2half_rn(WSCALE * __half2float(h));
    wf[base + 4 + grp*2 + p] = __float2half_rn(WSCALE * r);
}

// ---------------- prep kernels (folding, as validated in R1) ----------------
__global__ void prep0_kernel(const float* __restrict__ proj_b) {
    int t = blockIdx.x, m = threadIdx.x;
    int i2 = m & ~1;
    double div = exp((double)i2 * (-log(100000.0)) / (double)H);
    double arg = (double)(t + 1) * div;
    double pe = (m & 1) ? cos(arg) : sin(arg);
    g_hb[t*H + m] = proj_b[m] + (float)pe;
}

__global__ void prep1_kernel(const float* __restrict__ proj_w,
                             const float* __restrict__ q_w,
                             const float* __restrict__ k_w,
                             const float* __restrict__ v_w,
                             const float* __restrict__ res_w) {
    int c = blockIdx.x, j = threadIdx.x;
    float sq = 0.f, sk = 0.f, sv = 0.f;
    for (int m = 0; m < H; m++) {
        float p = proj_w[m*H + j];
        sq = fmaf(q_w[c*H + m], p, sq);
        sk = fmaf(k_w[c*H + m], p, sk);
        sv = fmaf(v_w[c*H + m], p, sv);
    }
    writeFrag<8>(g_wqF, c, j, sq);
    writeFrag<8>(g_wkF, c, j, sk);
    g_tmpVP[c*H + j] = sv;
    if (j < NIN) writeFrag<4>(g_wrF, c, j, res_w[c*NIN + j]);
    if (j < T) {
        float a = 0.f, b = 0.f, vv = 0.f;
        for (int m = 0; m < H; m++) {
            float hb = g_hb[j*H + m];
            a  = fmaf(q_w[c*H + m], hb, a);
            b  = fmaf(k_w[c*H + m], hb, b);
            vv = fmaf(v_w[c*H + m], hb, vv);
        }
        g_cq[j*H + c] = a;
        g_ck[j*H + c] = b;
        g_cvt[j*H + c] = vv;
    }
}

__global__ void prep2_kernel(const float* __restrict__ fc_w) {
    int c = blockIdx.x, j = threadIdx.x;
    float s = 0.f;
    for (int m = 0; m < H; m++) s = fmaf(fc_w[c*H + m], g_tmpVP[m*H + j], s);
    writeFrag<8>(g_wvF, c, j, s);
    if (j < T) {
        float s2 = 0.f;
        for (int m = 0; m < H; m++) s2 = fmaf(fc_w[c*H + m], g_cvt[j*H + m], s2);
        g_cv[j*H + c] = s2;
    }
}

// ---------------- mma helpers ----------------
__device__ __forceinline__ void mma16816(float* c, const uint32_t* a,
                                         uint32_t b0, uint32_t b1) {
    asm volatile(
        "mma.sync.aligned.m16n8k16.row.col.f32.f16.f16.f32 "
        "{%0,%1,%2,%3},{%4,%5,%6,%7},{%8,%9},{%0,%1,%2,%3};\n"
        : "+f"(c[0]), "+f"(c[1]), "+f"(c[2]), "+f"(c[3])
        : "r"(a[0]), "r"(a[1]), "r"(a[2]), "r"(a[3]), "r"(b0), "r"(b1));
}

__device__ __forceinline__ uint32_t pack2(__half a, __half b) {
    __half2 t = __halves2half2(a, b);
    return *reinterpret_cast<uint32_t*>(&t);
}

// warp-level GEMM: 16 rows x 128 cols, K = KT*16; A fp32 frags in warp-private
// SMEM (lane reads only its own slots), W in gmem fragment layout (L1-hot).
// 3 passes: Ahi*Whi + Ahi*Wlo + Alo*Whi, fp32 accum.
template<int KT>
__device__ __forceinline__ void wgemm(float acc[16][4], const float* aW,
                                      const __half* wf, int lane) {
    const uint4* w4 = (const uint4*)wf;
#pragma unroll
    for (int kt = 0; kt < KT; kt++) {
        uint32_t ahi[4], alo[4];
#pragma unroll
        for (int p = 0; p < 4; p++) {
            float2 v = *(const float2*)(aW + (kt*4 + p)*64 + lane*2);
            __half hx = __float2half_rn(v.x), hy = __float2half_rn(v.y);
            ahi[p] = pack2(hx, hy);
            alo[p] = pack2(__float2half_rn(v.x - __half2float(hx)),
                           __float2half_rn(v.y - __half2float(hy)));
        }
#pragma unroll
        for (int nt = 0; nt < 16; nt++) {
            uint4 b = __ldg(&w4[(nt*KT + kt)*32 + lane]);
            mma16816(acc[nt], ahi, b.x, b.y);   // hi*hi
            mma16816(acc[nt], ahi, b.z, b.w);   // hi*lo
            mma16816(acc[nt], alo, b.x, b.y);   // lo*hi
        }
    }
}

__device__ __forceinline__ void scale_bias(float acc[16][4],
                                           const float* __restrict__ cb,
                                           int tq, int j) {
#pragma unroll
    for (int nt = 0; nt < 16; nt++) {
        float2 b = __ldg((const float2*)(cb + tq*H + nt*8 + j*2));
        acc[nt][0] = acc[nt][0]*WSCALE_INV + b.x;
        acc[nt][1] = acc[nt][1]*WSCALE_INV + b.y;
        acc[nt][2] = acc[nt][2]*WSCALE_INV + b.x;
        acc[nt][3] = acc[nt][3]*WSCALE_INV + b.y;
    }
}

// ---------------- main kernel: 16 nodes/CTA, 8 warps, warp = 2 nodes -------
__global__ void __launch_bounds__(256, 1) htgnn_main(
    const float* __restrict__ inter, const float* __restrict__ x,
    const float* __restrict__ fc_b, const float* __restrict__ res_b,
    const float* __restrict__ res_alpha, const float* __restrict__ ln_g,
    const float* __restrict__ ln_b, float* __restrict__ out)
{
    extern __shared__ __align__(16) float aS[];   // 8KB per warp, warp-private
    const int tid = threadIdx.x;
    const int w = tid >> 5, lane = tid & 31;
    const int q = lane >> 2, j = lane & 3;        // tq = q, col-sub = j
    const int node0 = blockIdx.x * 16;
    const int na = node0 + 2*w, nb = na + 1;
    float* aW = aS + w*2048;
    const unsigned FULL = 0xffffffffu;

    // ---- stage A (inter) frags: lane writes/reads only its own slots ----
#pragma unroll
    for (int kt = 0; kt < 8; kt++)
#pragma unroll
        for (int p = 0; p < 4; p++) {
            int node = (p & 1) ? nb : na;
            int k = kt*16 + ((p >> 1) & 1)*8 + j*2;
            *(float2*)(aW + (kt*4 + p)*64 + lane*2) =
                *(const float2*)(inter + ((size_t)q*NN + node)*H + k);
        }

    // ---- Q ----
    float qacc[16][4] = {};
    wgemm<8>(qacc, aW, g_wqF, lane);
    scale_bias(qacc, g_cq, q, j);

    // ---- K ----
    float kacc[16][4] = {};
    wgemm<8>(kacc, aW, g_wkF, lane);
    scale_bias(kacc, g_ck, q, j);

    // ---- scores + softmax (warp-local, shfl) ----
    float pa[8], pb[8];
    {
        float sa[8], sb[8];
#pragma unroll
        for (int s = 0; s < 8; s++) {
            int src = (((q + s) & 7) << 2) | j;
            float da = 0.f, db = 0.f;
#pragma unroll
            for (int nt = 0; nt < 16; nt++) {
                da = fmaf(qacc[nt][0], __shfl_sync(FULL, kacc[nt][0], src), da);
                da = fmaf(qacc[nt][1], __shfl_sync(FULL, kacc[nt][1], src), da);
                db = fmaf(qacc[nt][2], __shfl_sync(FULL, kacc[nt][2], src), db);
                db = fmaf(qacc[nt][3], __shfl_sync(FULL, kacc[nt][3], src), db);
            }
            da += __shfl_xor_sync(FULL, da, 1);
            da += __shfl_xor_sync(FULL, da, 2);
            db += __shfl_xor_sync(FULL, db, 1);
            db += __shfl_xor_sync(FULL, db, 2);
            sa[s] = da; sb[s] = db;
        }
        float ma = sa[0], mb = sb[0];
#pragma unroll
        for (int s = 1; s < 8; s++) { ma = fmaxf(ma, sa[s]); mb = fmaxf(mb, sb[s]); }
        float za = 0.f, zb = 0.f;
#pragma unroll
        for (int s = 0; s < 8; s++) {
            pa[s] = expf(sa[s] - ma); za += pa[s];
            pb[s] = expf(sb[s] - mb); zb += pb[s];
        }
        float ia = 1.f/za, ib = 1.f/zb;
#pragma unroll
        for (int s = 0; s < 8; s++) { pa[s] *= ia; pb[s] *= ib; }
    }

    // ---- V (fc folded) ----
    float vacc[16][4] = {};
    wgemm<8>(vacc, aW, g_wvF, lane);
    scale_bias(vacc, g_cv, q, j);

    // ---- O = S @ V (shfl) ----
    float oacc[16][4] = {};
#pragma unroll
    for (int s = 0; s < 8; s++) {
        int src = (((q + s) & 7) << 2) | j;
        float wa = pa[s], wb = pb[s];
#pragma unroll
        for (int nt = 0; nt < 16; nt++) {
            oacc[nt][0] = fmaf(wa, __shfl_sync(FULL, vacc[nt][0], src), oacc[nt][0]);
            oacc[nt][1] = fmaf(wa, __shfl_sync(FULL, vacc[nt][1], src), oacc[nt][1]);
            oacc[nt][2] = fmaf(wb, __shfl_sync(FULL, vacc[nt][2], src), oacc[nt][2]);
            oacc[nt][3] = fmaf(wb, __shfl_sync(FULL, vacc[nt][3], src), oacc[nt][3]);
        }
    }

    // ---- stage x frags (overwrites aW; warp-serial, safe) + res GEMM ----
#pragma unroll
    for (int kt = 0; kt < 4; kt++)
#pragma unroll
        for (int p = 0; p < 4; p++) {
            int node = (p & 1) ? nb : na;
            int k = kt*16 + ((p >> 1) & 1)*8 + j*2;
            *(float2*)(aW + (kt*4 + p)*64 + lane*2) =
                *(const float2*)(x + ((size_t)q*NN + node)*NIN + k);
        }
    float racc[16][4] = {};
    wgemm<4>(racc, aW, g_wrF, lane);

    // ---- epilogue: relu/gate/LN/store ----
    float alpha = 1.f / (1.f + expf(-__ldg(res_alpha)));
    float beta = 1.f - alpha;
    float sua = 0.f, sqa = 0.f, sub = 0.f, sqb = 0.f;
#pragma unroll
    for (int nt = 0; nt < 16; nt++) {
        int c = nt*8 + j*2;
        float2 fb = __ldg((const float2*)(fc_b + c));
        float2 rb = __ldg((const float2*)(res_b + c));
        float v0 = fmaxf(oacc[nt][0] + fb.x, 0.f)*alpha +
                   (racc[nt][0]*WSCALE_INV + rb.x)*beta;
        float v1 = fmaxf(oacc[nt][1] + fb.y, 0.f)*alpha +
                   (racc[nt][1]*WSCALE_INV + rb.y)*beta;
        float v2 = fmaxf(oacc[nt][2] + fb.x, 0.f)*alpha +
                   (racc[nt][2]*WSCALE_INV + rb.x)*beta;
        float v3 = fmaxf(oacc[nt][3] + fb.y, 0.f)*alpha +
                   (racc[nt][3]*WSCALE_INV + rb.y)*beta;
        oacc[nt][0] = v0; oacc[nt][1] = v1; oacc[nt][2] = v2; oacc[nt][3] = v3;
        sua += v0 + v1; sqa += v0*v0 + v1*v1;
        sub += v2 + v3; sqb += v2*v2 + v3*v3;
    }
    sua += __shfl_xor_sync(FULL, sua, 1); sua += __shfl_xor_sync(FULL, sua, 2);
    sqa += __shfl_xor_sync(FULL, sqa, 1); sqa += __shfl_xor_sync(FULL, sqa, 2);
    sub += __shfl_xor_sync(FULL, sub, 1); sub += __shfl_xor_sync(FULL, sub, 2);
    sqb += __shfl_xor_sync(FULL, sqb, 1); sqb += __shfl_xor_sync(FULL, sqb, 2);
    float mua = sua * (1.f/128.f);
    float mub = sub * (1.f/128.f);
    float inva = rsqrtf(sqa*(1.f/128.f) - mua*mua + LN_EPS);
    float invb = rsqrtf(sqb*(1.f/128.f) - mub*mub + LN_EPS);

    float* outa = out + ((size_t)q*NN + na)*H;
    float* outb = out + ((size_t)q*NN + nb)*H;
#pragma unroll
    for (int nt = 0; nt < 16; nt++) {
        int c = nt*8 + j*2;
        float2 lg = __ldg((const float2*)(ln_g + c));
        float2 lb = __ldg((const float2*)(ln_b + c));
        float2 oa = make_float2((oacc[nt][0] - mua)*inva*lg.x + lb.x,
                                (oacc[nt][1] - mua)*inva*lg.y + lb.y);
        float2 ob = make_float2((oacc[nt][2] - mub)*invb*lg.x + lb.x,
                                (oacc[nt][3] - mub)*invb*lg.y + lb.y);
        *(float2*)(outa + c) = oa;
        *(float2*)(outb + c) = ob;
    }
}

extern "C" void kernel_launch(void* const* d_in, const int* in_sizes, int n_in,
                              void* d_out, int out_size) {
    (void)in_sizes; (void)n_in; (void)out_size;
    const float* inter     = (const float*)d_in[0];
    const float* x         = (const float*)d_in[1];
    const float* proj_w    = (const float*)d_in[2];
    const float* proj_b    = (const float*)d_in[3];
    const float* q_w       = (const float*)d_in[4];
    const float* k_w       = (const float*)d_in[5];
    const float* v_w       = (const float*)d_in[6];
    const float* fc_w      = (const float*)d_in[7];
    const float* fc_b      = (const float*)d_in[8];
    const float* res_w     = (const float*)d_in[9];
    const float* res_b     = (const float*)d_in[10];
    const float* res_alpha = (const float*)d_in[11];
    const float* ln_g      = (const float*)d_in[12];
    const float* ln_b      = (const float*)d_in[13];
    float* out = (float*)d_out;

    cudaFuncSetAttribute(htgnn_main, cudaFuncAttributeMaxDynamicSharedMemorySize,
                         65536);

    prep0_kernel<<<T, H>>>(proj_b);
    prep1_kernel<<<H, H>>>(proj_w, q_w, k_w, v_w, res_w);
    prep2_kernel<<<H, H>>>(fc_w);
    htgnn_main<<<NN/16, 256, 65536>>>(inter, x, fc_b, res_b, res_alpha,
                                      ln_g, ln_b, out);
}

// round 5
// speedup vs baseline: 3.9932x; 1.2753x over previous
#include <cuda_runtime.h>
#include <cuda_fp16.h>
#include <math.h>
#include <stdint.h>

#define T 8
#define NN 100000
#define H 128
#define NIN 64
#define LN_EPS 1e-5f
#define WSCALE 64.f
#define WSCALE_INV 0.015625f

// ---------------- folded weights in mma-B-fragment layout (hi-only) --------
// slot idx = ((nt*KT+kt)*32+lane)*4 + grp*2 + p   (uint2 per lane-slot)
// nt=n/8, kt=k/16, lane=((n&7)<<2)|((k>>1)&3), grp=(k>>3)&1, p=k&1
__device__ __align__(8) __half g_wqF[16*8*32*4];
__device__ __align__(8) __half g_wkF[16*8*32*4];
__device__ __align__(8) __half g_wvF[16*8*32*4];
__device__ __align__(8) __half g_wrF[16*4*32*4];
__device__ float g_cq[T*H], g_ck[T*H], g_cv[T*H];   // [t][c]
__device__ float g_hb[T*H];
__device__ float g_tmpVP[H*H];
__device__ float g_cvt[T*H];

template<int KT>
__device__ __forceinline__ void writeFrag(__half* wf, int n, int k, float w) {
    int nt = n >> 3, kt = k >> 4;
    int lane = ((n & 7) << 2) | ((k >> 1) & 3);
    int grp = (k >> 3) & 1, p = k & 1;
    wf[((nt*KT + kt)*32 + lane)*4 + grp*2 + p] = __float2half_rn(WSCALE * w);
}

// ---------------- prep kernels ----------------
__global__ void prep0_kernel(const float* __restrict__ proj_b) {
    int t = blockIdx.x, m = threadIdx.x;
    int i2 = m & ~1;
    double div = exp((double)i2 * (-log(100000.0)) / (double)H);
    double arg = (double)(t + 1) * div;
    double pe = (m & 1) ? cos(arg) : sin(arg);
    g_hb[t*H + m] = proj_b[m] + (float)pe;
}

__global__ void prep1_kernel(const float* __restrict__ proj_w,
                             const float* __restrict__ q_w,
                             const float* __restrict__ k_w,
                             const float* __restrict__ v_w,
                             const float* __restrict__ res_w) {
    int c = blockIdx.x, j = threadIdx.x;
    float sq = 0.f, sk = 0.f, sv = 0.f;
    for (int m = 0; m < H; m++) {
        float p = proj_w[m*H + j];
        sq = fmaf(q_w[c*H + m], p, sq);
        sk = fmaf(k_w[c*H + m], p, sk);
        sv = fmaf(v_w[c*H + m], p, sv);
    }
    writeFrag<8>(g_wqF, c, j, sq);
    writeFrag<8>(g_wkF, c, j, sk);
    g_tmpVP[c*H + j] = sv;
    if (j < NIN) writeFrag<4>(g_wrF, c, j, res_w[c*NIN + j]);
    if (j < T) {
        float a = 0.f, b = 0.f, vv = 0.f;
        for (int m = 0; m < H; m++) {
            float hb = g_hb[j*H + m];
            a  = fmaf(q_w[c*H + m], hb, a);
            b  = fmaf(k_w[c*H + m], hb, b);
            vv = fmaf(v_w[c*H + m], hb, vv);
        }
        g_cq[j*H + c] = a;
        g_ck[j*H + c] = b;
        g_cvt[j*H + c] = vv;
    }
}

__global__ void prep2_kernel(const float* __restrict__ fc_w) {
    int c = blockIdx.x, j = threadIdx.x;
    float s = 0.f;
    for (int m = 0; m < H; m++) s = fmaf(fc_w[c*H + m], g_tmpVP[m*H + j], s);
    writeFrag<8>(g_wvF, c, j, s);
    if (j < T) {
        float s2 = 0.f;
        for (int m = 0; m < H; m++) s2 = fmaf(fc_w[c*H + m], g_cvt[j*H + m], s2);
        g_cv[j*H + c] = s2;
    }
}

// ---------------- mma helpers ----------------
__device__ __forceinline__ void mma16816(float* c, const uint32_t* a,
                                         uint32_t b0, uint32_t b1) {
    asm volatile(
        "mma.sync.aligned.m16n8k16.row.col.f32.f16.f16.f32 "
        "{%0,%1,%2,%3},{%4,%5,%6,%7},{%8,%9},{%0,%1,%2,%3};\n"
        : "+f"(c[0]), "+f"(c[1]), "+f"(c[2]), "+f"(c[3])
        : "r"(a[0]), "r"(a[1]), "r"(a[2]), "r"(a[3]), "r"(b0), "r"(b1));
}

__device__ __forceinline__ uint32_t pack2(__half a, __half b) {
    __half2 t = __halves2half2(a, b);
    return *reinterpret_cast<uint32_t*>(&t);
}

// warp GEMM: 16 rows x 128 cols, K=KT*16. 2-pass (Ahi*W + Alo*W), fp32 accum.
// Pass-major per kt: 16 independent MMAs per pass; b frags cached in regs.
template<int KT>
__device__ __forceinline__ void wgemm(float acc[16][4], const float* aW,
                                      const __half* wf, int lane) {
    const uint2* w2 = (const uint2*)wf;
#pragma unroll
    for (int kt = 0; kt < KT; kt++) {
        uint32_t ahi[4], alo[4];
#pragma unroll
        for (int p = 0; p < 4; p++) {
            float2 v = *(const float2*)(aW + (kt*4 + p)*64 + lane*2);
            __half hx = __float2half_rn(v.x), hy = __float2half_rn(v.y);
            ahi[p] = pack2(hx, hy);
            alo[p] = pack2(__float2half_rn(v.x - __half2float(hx)),
                           __float2half_rn(v.y - __half2float(hy)));
        }
        uint2 b[16];
#pragma unroll
        for (int nt = 0; nt < 16; nt++) {
            b[nt] = __ldg(&w2[(nt*KT + kt)*32 + lane]);
            mma16816(acc[nt], ahi, b[nt].x, b[nt].y);
        }
#pragma unroll
        for (int nt = 0; nt < 16; nt++)
            mma16816(acc[nt], alo, b[nt].x, b[nt].y);
    }
}

__device__ __forceinline__ void scale_bias(float acc[16][4],
                                           const float* __restrict__ cb,
                                           int tq, int j) {
#pragma unroll
    for (int nt = 0; nt < 16; nt++) {
        float2 b = __ldg((const float2*)(cb + tq*H + nt*8 + j*2));
        acc[nt][0] = acc[nt][0]*WSCALE_INV + b.x;
        acc[nt][1] = acc[nt][1]*WSCALE_INV + b.y;
        acc[nt][2] = acc[nt][2]*WSCALE_INV + b.x;
        acc[nt][3] = acc[nt][3]*WSCALE_INV + b.y;
    }
}

// ---------------- main kernel: 16 nodes/CTA, 8 warps, warp = 2 nodes -------
__global__ void __launch_bounds__(256, 1) htgnn_main(
    const float* __restrict__ inter, const float* __restrict__ x,
    const float* __restrict__ fc_b, const float* __restrict__ res_b,
    const float* __restrict__ res_alpha, const float* __restrict__ ln_g,
    const float* __restrict__ ln_b, float* __restrict__ out)
{
    extern __shared__ __align__(16) float aS[];   // 8KB per warp, warp-private
    const int tid = threadIdx.x;
    const int w = tid >> 5, lane = tid & 31;
    const int q = lane >> 2, j = lane & 3;
    const int node0 = blockIdx.x * 16;
    const int na = node0 + 2*w, nb = na + 1;
    float* aW = aS + w*2048;
    const unsigned FULL = 0xffffffffu;

    // ---- stage A (inter) frags ----
#pragma unroll
    for (int kt = 0; kt < 8; kt++)
#pragma unroll
        for (int p = 0; p < 4; p++) {
            int node = (p & 1) ? nb : na;
            int k = kt*16 + ((p >> 1) & 1)*8 + j*2;
            *(float2*)(aW + (kt*4 + p)*64 + lane*2) =
                *(const float2*)(inter + ((size_t)q*NN + node)*H + k);
        }

    // ---- Q ----
    float qacc[16][4] = {};
    wgemm<8>(qacc, aW, g_wqF, lane);
    scale_bias(qacc, g_cq, q, j);

    // ---- K ----
    float kacc[16][4] = {};
    wgemm<8>(kacc, aW, g_wkF, lane);
    scale_bias(kacc, g_ck, q, j);

    // ---- scores + softmax (warp-local, shfl) ----
    float pa[8], pb[8];
    {
        float sa[8], sb[8];
#pragma unroll
        for (int s = 0; s < 8; s++) {
            int src = (((q + s) & 7) << 2) | j;
            float da = 0.f, db = 0.f;
#pragma unroll
            for (int nt = 0; nt < 16; nt++) {
                da = fmaf(qacc[nt][0], __shfl_sync(FULL, kacc[nt][0], src), da);
                da = fmaf(qacc[nt][1], __shfl_sync(FULL, kacc[nt][1], src), da);
                db = fmaf(qacc[nt][2], __shfl_sync(FULL, kacc[nt][2], src), db);
                db = fmaf(qacc[nt][3], __shfl_sync(FULL, kacc[nt][3], src), db);
            }
            da += __shfl_xor_sync(FULL, da, 1);
            da += __shfl_xor_sync(FULL, da, 2);
            db += __shfl_xor_sync(FULL, db, 1);
            db += __shfl_xor_sync(FULL, db, 2);
            sa[s] = da; sb[s] = db;
        }
        float ma = sa[0], mb = sb[0];
#pragma unroll
        for (int s = 1; s < 8; s++) { ma = fmaxf(ma, sa[s]); mb = fmaxf(mb, sb[s]); }
        float za = 0.f, zb = 0.f;
#pragma unroll
        for (int s = 0; s < 8; s++) {
            pa[s] = expf(sa[s] - ma); za += pa[s];
            pb[s] = expf(sb[s] - mb); zb += pb[s];
        }
        float ia = 1.f/za, ib = 1.f/zb;
#pragma unroll
        for (int s = 0; s < 8; s++) { pa[s] *= ia; pb[s] *= ib; }
    }

    // ---- V (fc folded) ----
    float vacc[16][4] = {};
    wgemm<8>(vacc, aW, g_wvF, lane);
    scale_bias(vacc, g_cv, q, j);

    // ---- O = S @ V (shfl) ----
    float oacc[16][4] = {};
#pragma unroll
    for (int s = 0; s < 8; s++) {
        int src = (((q + s) & 7) << 2) | j;
        float wa = pa[s], wb = pb[s];
#pragma unroll
        for (int nt = 0; nt < 16; nt++) {
            oacc[nt][0] = fmaf(wa, __shfl_sync(FULL, vacc[nt][0], src), oacc[nt][0]);
            oacc[nt][1] = fmaf(wa, __shfl_sync(FULL, vacc[nt][1], src), oacc[nt][1]);
            oacc[nt][2] = fmaf(wb, __shfl_sync(FULL, vacc[nt][2], src), oacc[nt][2]);
            oacc[nt][3] = fmaf(wb, __shfl_sync(FULL, vacc[nt][3], src), oacc[nt][3]);
        }
    }

    // ---- stage x frags (overwrites aW; warp-private, safe) + res GEMM ----
    __syncwarp();
#pragma unroll
    for (int kt = 0; kt < 4; kt++)
#pragma unroll
        for (int p = 0; p < 4; p++) {
            int node = (p & 1) ? nb : na;
            int k = kt*16 + ((p >> 1) & 1)*8 + j*2;
            *(float2*)(aW + (kt*4 + p)*64 + lane*2) =
                *(const float2*)(x + ((size_t)q*NN + node)*NIN + k);
        }
    float racc[16][4] = {};
    wgemm<4>(racc, aW, g_wrF, lane);

    // ---- epilogue: relu/gate/LN/store ----
    float alpha = 1.f / (1.f + expf(-__ldg(res_alpha)));
    float beta = 1.f - alpha;
    float sua = 0.f, sqa = 0.f, sub = 0.f, sqb = 0.f;
#pragma unroll
    for (int nt = 0; nt < 16; nt++) {
        int c = nt*8 + j*2;
        float2 fb = __ldg((const float2*)(fc_b + c));
        float2 rb = __ldg((const float2*)(res_b + c));
        float v0 = fmaxf(oacc[nt][0] + fb.x, 0.f)*alpha +
                   (racc[nt][0]*WSCALE_INV + rb.x)*beta;
        float v1 = fmaxf(oacc[nt][1] + fb.y, 0.f)*alpha +
                   (racc[nt][1]*WSCALE_INV + rb.y)*beta;
        float v2 = fmaxf(oacc[nt][2] + fb.x, 0.f)*alpha +
                   (racc[nt][2]*WSCALE_INV + rb.x)*beta;
        float v3 = fmaxf(oacc[nt][3] + fb.y, 0.f)*alpha +
                   (racc[nt][3]*WSCALE_INV + rb.y)*beta;
        oacc[nt][0] = v0; oacc[nt][1] = v1; oacc[nt][2] = v2; oacc[nt][3] = v3;
        sua += v0 + v1; sqa += v0*v0 + v1*v1;
        sub += v2 + v3; sqb += v2*v2 + v3*v3;
    }
    sua += __shfl_xor_sync(FULL, sua, 1); sua += __shfl_xor_sync(FULL, sua, 2);
    sqa += __shfl_xor_sync(FULL, sqa, 1); sqa += __shfl_xor_sync(FULL, sqa, 2);
    sub += __shfl_xor_sync(FULL, sub, 1); sub += __shfl_xor_sync(FULL, sub, 2);
    sqb += __shfl_xor_sync(FULL, sqb, 1); sqb += __shfl_xor_sync(FULL, sqb, 2);
    float mua = sua * (1.f/128.f);
    float mub = sub * (1.f/128.f);
    float inva = rsqrtf(sqa*(1.f/128.f) - mua*mua + LN_EPS);
    float invb = rsqrtf(sqb*(1.f/128.f) - mub*mub + LN_EPS);

    float* outa = out + ((size_t)q*NN + na)*H;
    float* outb = out + ((size_t)q*NN + nb)*H;
#pragma unroll
    for (int nt = 0; nt < 16; nt++) {
        int c = nt*8 + j*2;
        float2 lg = __ldg((const float2*)(ln_g + c));
        float2 lb = __ldg((const float2*)(ln_b + c));
        float2 oa = make_float2((oacc[nt][0] - mua)*inva*lg.x + lb.x,
                                (oacc[nt][1] - mua)*inva*lg.y + lb.y);
        float2 ob = make_float2((oacc[nt][2] - mub)*invb*lg.x + lb.x,
                                (oacc[nt][3] - mub)*invb*lg.y + lb.y);
        *(float2*)(outa + c) = oa;
        *(float2*)(outb + c) = ob;
    }
}

extern "C" void kernel_launch(void* const* d_in, const int* in_sizes, int n_in,
                              void* d_out, int out_size) {
    (void)in_sizes; (void)n_in; (void)out_size;
    const float* inter     = (const float*)d_in[0];
    const float* x         = (const float*)d_in[1];
    const float* proj_w    = (const float*)d_in[2];
    const float* proj_b    = (const float*)d_in[3];
    const float* q_w       = (const float*)d_in[4];
    const float* k_w       = (const float*)d_in[5];
    const float* v_w       = (const float*)d_in[6];
    const float* fc_w      = (const float*)d_in[7];
    const float* fc_b      = (const float*)d_in[8];
    const float* res_w     = (const float*)d_in[9];
    const float* res_b     = (const float*)d_in[10];
    const float* res_alpha = (const float*)d_in[11];
    const float* ln_g      = (const float*)d_in[12];
    const float* ln_b      = (const float*)d_in[13];
    float* out = (float*)d_out;

    cudaFuncSetAttribute(htgnn_main, cudaFuncAttributeMaxDynamicSharedMemorySize,
                         65536);

    prep0_kernel<<<T, H>>>(proj_b);
    prep1_kernel<<<H, H>>>(proj_w, q_w, k_w, v_w, res_w);
    prep2_kernel<<<H, H>>>(fc_w);
    htgnn_main<<<NN/16, 256, 65536>>>(inter, x, fc_b, res_b, res_alpha,
                                      ln_g, ln_b, out);
}